// round 11
// baseline (speedup 1.0000x reference)
#include <cuda_runtime.h>
#include <cuda_fp16.h>
#include <cstdint>

// ============================================================
// Conv2d 3x3 s1 p1: x(32,128,56,56)*W(256,128,3,3)+b -> (32,256,56,56)
// Shifted-GEMM conv on mma.sync.m16n8k16.f32.f16.f16.f32.
// R11: pad kernel deleted. A halo windows are staged directly from
// raw x (masked scalar LDG + fp16 convert + STS.128), zero border and
// slack produced by the same predicate. Mainloop identical to R10:
// 9 quad windows (1 barrier / 4 shift-rounds), B ring of 2 quad
// buffers staged post-barrier, A double-buffered (windows 0/3/5).
// CTA = 128 px x 128 couts, 256 thr, 2 CTAs/SM.
// ============================================================

#define HW        56
#define PW        58
#define CIN       128
#define COUT      256
#define BATCH     32
#define MTILES    26
#define NWIN      9             // 36 shift-rounds as 9 quad windows
#define AQ        248           // A smem q-stride (half2 units)
#define SA_BYTES  (16 * AQ * 4) // 15872 per A buffer
#define ABUFS     (2 * SA_BYTES)
#define SBQ_BYTES 32768         // B quad buffer (4 rounds x 8KB)
#define SMEM_TOTAL (ABUFS + 2 * SBQ_BYTES)   // 97280

__device__ uint32_t g_wrfh[2 * 4 * 9 * 2048];   // W in mma fragment order (half2)

#define N_WRF  (2 * 4 * 9 * 2048)

// ---------------- W prep (fragment-order half2) ----------------
// block = (nb*4+chunk)*9+s (2048 u32); u4 = ((p*2+kt)*32+lane), word j:
//   nt = p*2+(j>>1), reg = j&1
//   half2 = ( W[n][c], W[n][c+1] ), n = nb*128+nt*8+lane/4,
//   c = chunk*32 + kt*16 + (lane&3)*2 + reg*8
__global__ void wrf_kernel(const float* __restrict__ W) {
    int idx = blockIdx.x * blockDim.x + threadIdx.x;
    if (idx >= N_WRF) return;
    int blk = idx >> 11, within = idx & 2047;
    int s = blk % 9, t = blk / 9;
    int chunk = t & 3, nb = t >> 2;
    int u4 = within >> 2, j = within & 3;
    int lane = u4 & 31, t2 = u4 >> 5;
    int kt = t2 & 1, p = t2 >> 1;
    int nt = p * 2 + (j >> 1), reg = j & 1;
    int n = nb * 128 + nt * 8 + (lane >> 2);
    int c = chunk * 32 + kt * 16 + (lane & 3) * 2 + reg * 8;
    __half2 hv = __floats2half2_rn(W[(n * CIN + c) * 9 + s],
                                   W[(n * CIN + c + 1) * 9 + s]);
    g_wrfh[idx] = *(uint32_t*)&hv;
}

// ---------------- helpers ----------------
__device__ __forceinline__ void mma_f16(float* d, const uint32_t* a, const uint32_t* b) {
    asm volatile(
        "mma.sync.aligned.m16n8k16.row.col.f32.f16.f16.f32 "
        "{%0,%1,%2,%3}, {%4,%5,%6,%7}, {%8,%9}, {%0,%1,%2,%3};"
        : "+f"(d[0]), "+f"(d[1]), "+f"(d[2]), "+f"(d[3])
        : "r"(a[0]), "r"(a[1]), "r"(a[2]), "r"(a[3]), "r"(b[0]), "r"(b[1]));
}
__device__ __forceinline__ void cp_async16(uint32_t sdst, const void* gsrc) {
    asm volatile("cp.async.cg.shared.global [%0], [%1], 16;" :: "r"(sdst), "l"(gsrc));
}
__device__ __forceinline__ uint32_t smem_u32(const void* p) {
    uint32_t a;
    asm("{ .reg .u64 t; cvta.to.shared.u64 t, %1; cvt.u32.u64 %0, t; }" : "=r"(a) : "l"(p));
    return a;
}
__device__ __forceinline__ int chunk_of(int r) {
    return (r >= 27) ? 3 : (r >= 18) ? 2 : (r >= 9) ? 1 : 0;
}

// one shift-round of MMA work (identical to R10)
__device__ __forceinline__ void compute_round(
    const char* smem, int chunk, int off, int bofs,
    int wm, int wn, int lane, float acc[2][8][4])
{
    const uint32_t* sA = (const uint32_t*)(smem + (chunk & 1) * SA_BYTES);
    const uint4* sB4 = (const uint4*)(smem + ABUFS + bofs);
    const int qb = off + wm * 32 + (lane >> 2);
    #pragma unroll
    for (int kt = 0; kt < 2; kt++) {
        const uint32_t* arow = sA + (kt * 8 + (lane & 3)) * AQ;
        uint32_t afr[2][4];
        #pragma unroll
        for (int mt = 0; mt < 2; mt++) {
            const int q = qb + mt * 16;
            afr[mt][0] = arow[q];
            afr[mt][1] = arow[q + 8];
            afr[mt][2] = arow[4 * AQ + q];
            afr[mt][3] = arow[4 * AQ + q + 8];
        }
        uint4 bfr[4];
        #pragma unroll
        for (int c4 = 0; c4 < 4; c4++)
            bfr[c4] = sB4[((wn * 4 + c4) * 2 + kt) * 32 + lane];
        #pragma unroll
        for (int mt = 0; mt < 2; mt++)
            #pragma unroll
            for (int c4 = 0; c4 < 4; c4++) {
                mma_f16(acc[mt][c4 * 2],     afr[mt], (const uint32_t*)&bfr[c4]);
                mma_f16(acc[mt][c4 * 2 + 1], afr[mt], ((const uint32_t*)&bfr[c4]) + 2);
            }
    }
}

// ---------------- main ----------------
__global__ void __launch_bounds__(256, 2)
conv_main(const float* __restrict__ x, const float* __restrict__ bias,
          float* __restrict__ out) {
    extern __shared__ char smem[];
    const uint32_t smem_b = smem_u32(smem);
    const int tid  = threadIdx.x;
    const int lane = tid & 31;
    const int wid  = tid >> 5;
    const int wm   = wid & 3;          // 4 m-warps: 32 px each
    const int wn   = wid >> 2;         // 2 n-warps: 64 couts each
    const int bb   = blockIdx.z;
    const int nb   = blockIdx.y;       // 0/1
    const int q0   = blockIdx.x * 128;

    const float* xb = x + (long)bb * CIN * (HW * HW);

    float acc[2][8][4];
    #pragma unroll
    for (int i = 0; i < 2; i++)
        #pragma unroll
        for (int j = 0; j < 8; j++)
            #pragma unroll
            for (int k = 0; k < 4; k++) acc[i][j][k] = 0.0f;

    // A stage directly from raw x: 16 c2-rows x 62 x (4 half2) into buffer sel.
    // Padded-domain pixel qq -> (h,w) in 58x58; interior maps to x[h-1][w-1],
    // border AND q-slack (qq > 3363) are zeroed by the same predicate.
    #define STAGE_A_RAW(chunk, sel)                                                \
        do {                                                                       \
            _Pragma("unroll")                                                      \
            for (int it = 0; it < 4; it++) {                                       \
                int aid = it * 256 + tid;                                          \
                if (aid < 16 * 62) {                                               \
                    int row = aid / 62, col = aid - row * 62;                      \
                    const float* xp0 = xb + (long)((chunk) * 32 + row * 2) * (HW * HW); \
                    const float* xp1 = xp0 + HW * HW;                              \
                    uint32_t o4[4];                                                \
                    const int qq = q0 + col * 4;                                   \
                    _Pragma("unroll")                                              \
                    for (int j = 0; j < 4; j++) {                                  \
                        int h = (qq + j) / PW, w = (qq + j) - h * PW;              \
                        float v0 = 0.f, v1 = 0.f;                                  \
                        if (h >= 1 && h <= HW && w >= 1 && w <= HW) {              \
                            int o = (h - 1) * HW + (w - 1);                        \
                            v0 = __ldg(xp0 + o); v1 = __ldg(xp1 + o);              \
                        }                                                          \
                        __half2 hv = __floats2half2_rn(v0, v1);                    \
                        o4[j] = *(uint32_t*)&hv;                                   \
                    }                                                              \
                    *(uint4*)(smem + (sel) * SA_BYTES + (row * AQ + col * 4) * 4) =\
                        make_uint4(o4[0], o4[1], o4[2], o4[3]);                    \
                }                                                                  \
            }                                                                      \
        } while (0)

    // stage B for one shift-round r into quad buffer ((r>>2)&1), slot (r&3)
    #define STAGE_B1(r)                                                            \
        do {                                                                       \
            const int ch = chunk_of(r), sh = (r) - 9 * ch;                         \
            const uint32_t* src = g_wrfh                                           \
                + ((size_t)((nb * 4 + ch) * 9 + sh)) * 2048 + tid * 4;             \
            uint32_t dst = smem_b + ABUFS + (((r) >> 2) & 1) * SBQ_BYTES           \
                           + ((r) & 3) * 8192 + tid * 16;                          \
            cp_async16(dst, src);                                                  \
            cp_async16(dst + 4096, src + 1024);                                    \
        } while (0)

    // prologue: window 0 data (B rounds 0..3 async, A chunk 0 synchronous)
    STAGE_B1(0); STAGE_B1(1); STAGE_B1(2); STAGE_B1(3);
    asm volatile("cp.async.commit_group;" ::: "memory");
    STAGE_A_RAW(0, 0);

    for (int w = 0; w < NWIN; w++) {
        // wait for this window's B (committed one window ago)
        asm volatile("cp.async.wait_group 0;" ::: "memory");
        __syncthreads();

        // stage next window AFTER the barrier (ring-2 safe: all warps past
        // this barrier finished window w-1, the only reader of (w+1)%2).
        // A targets: buf1 last read r17 (win 4) -> staged win 5; buf0 last
        // read r8 (win 2) -> staged win 3. STS visible after next barrier.
        if (w + 1 < NWIN) {
            const int r0 = 4 * (w + 1);
            STAGE_B1(r0); STAGE_B1(r0 + 1); STAGE_B1(r0 + 2); STAGE_B1(r0 + 3);
            asm volatile("cp.async.commit_group;" ::: "memory");
            if (w == 0)      STAGE_A_RAW(1, 1);
            else if (w == 3) STAGE_A_RAW(2, 0);
            else if (w == 5) STAGE_A_RAW(3, 1);
        }

        // compute rounds 4w .. 4w+3
        const int qbase = (w & 1) * SBQ_BYTES;
        #pragma unroll
        for (int j = 0; j < 4; j++) {
            const int r  = 4 * w + j;
            const int ch = chunk_of(r);
            const int s  = r - 9 * ch;
            compute_round(smem, ch, (s / 3) * PW + (s % 3), qbase + j * 8192,
                          wm, wn, lane, acc);
        }
    }

    // ---- epilogue ----
    const long obb = (long)bb * COUT * (HW * HW);
    #pragma unroll
    for (int nt = 0; nt < 8; nt++) {
        const int n = nb * 128 + wn * 64 + nt * 8 + (lane & 3) * 2;
        const float bv0 = __ldg(bias + n);
        const float bv1 = __ldg(bias + n + 1);
        const long onb = obb + (long)n * (HW * HW);
        #pragma unroll
        for (int mt = 0; mt < 2; mt++) {
            const int m = q0 + wm * 32 + mt * 16 + (lane >> 2);
            {
                const int h = m / PW, w = m % PW;
                if (h < HW && w < HW) {
                    const long o = onb + h * HW + w;
                    out[o]           = acc[mt][nt][0] + bv0;
                    out[o + HW * HW] = acc[mt][nt][1] + bv1;
                }
            }
            {
                const int m2 = m + 8;
                const int h = m2 / PW, w = m2 % PW;
                if (h < HW && w < HW) {
                    const long o = onb + h * HW + w;
                    out[o]           = acc[mt][nt][2] + bv0;
                    out[o + HW * HW] = acc[mt][nt][3] + bv1;
                }
            }
        }
    }
}

// ---------------- launch ----------------
extern "C" void kernel_launch(void* const* d_in, const int* in_sizes, int n_in,
                              void* d_out, int out_size) {
    const float* x  = (const float*)d_in[0];
    const float* W  = (const float*)d_in[1];
    const float* bi = (const float*)d_in[2];
    float* out      = (float*)d_out;

    cudaFuncSetAttribute(conv_main, cudaFuncAttributeMaxDynamicSharedMemorySize,
                         SMEM_TOTAL);

    wrf_kernel<<<(N_WRF + 255) / 256, 256>>>(W);
    conv_main<<<dim3(MTILES, 2, BATCH), 256, SMEM_TOTAL>>>(x, bi, out);
}

// round 12
// speedup vs baseline: 1.0946x; 1.0946x over previous
#include <cuda_runtime.h>
#include <cuda_fp16.h>
#include <cstdint>

// ============================================================
// Conv2d 3x3 s1 p1: x(32,128,56,56)*W(256,128,3,3)+b -> (32,256,56,56)
// Shifted-GEMM conv on mma.sync.m16n8k16.f32.f16.f16.f32.
// R12 = R10 (best: 166.1us) + :
//  - border/slack zeroing deleted (device globals are zero-initialized
//    at module load; interior copy never touches border cells, so the
//    zero border persists across graph replays)
//  - window body reordered: round 0 computes first, THEN next-window
//    staging is issued (hides staging issue cost under HMMAs; all
//    ring-safety arguments unchanged - staging still post-barrier)
// Mainloop: 9 quad windows (1 barrier / 4 shift-rounds), B ring of 2
// quad buffers, A double-buffered per 32-cin chunk (halo 248 px).
// CTA = 128 px x 128 couts, 256 thr, 2 CTAs/SM.
// ============================================================

#define HW        56
#define PW        58
#define CSTRIDE   3584          // half2 units per (b,c2) slice
#define CIN       128
#define COUT      256
#define BATCH     32
#define MTILES    26
#define NWIN      9             // 36 shift-rounds as 9 quad windows
#define AQ        248           // A smem q-stride (half2 units)
#define SA_BYTES  (16 * AQ * 4) // 15872 per A buffer
#define ABUFS     (2 * SA_BYTES)
#define SBQ_BYTES 32768         // B quad buffer (4 rounds x 8KB)
#define SMEM_TOTAL (ABUFS + 2 * SBQ_BYTES)   // 97280

__device__ __half2  g_xpadh[BATCH * 64 * CSTRIDE];   // zero-init at load;
                                                     // border/slack never written
__device__ uint32_t g_wrfh[2 * 4 * 9 * 2048];        // W fragment order (half2)

#define N_COPY (32 * 64 * 56 * 14)
#define N_WRF  (2 * 4 * 9 * 2048)

// ---------------- fused prep: interior copy + W fragments ----------------
__global__ void prep_kernel(const float* __restrict__ x, const float* __restrict__ W) {
    int id = blockIdx.x * blockDim.x + threadIdx.x;
    if (id < N_COPY) {
        int f4  = id % 14;
        int h   = (id / 14) % 56;
        int bc2 = id / (14 * 56);          // b*64 + c2
        const float* p0 = x + ((long)bc2 * 2) * 3136 + h * 56 + f4 * 4;
        float4 v0 = *(const float4*)p0;
        float4 v1 = *(const float4*)(p0 + 3136);
        __half2* d = g_xpadh + (long)bc2 * CSTRIDE + (h + 1) * PW + 1 + f4 * 4;
        d[0] = __floats2half2_rn(v0.x, v1.x);
        d[1] = __floats2half2_rn(v0.y, v1.y);
        d[2] = __floats2half2_rn(v0.z, v1.z);
        d[3] = __floats2half2_rn(v0.w, v1.w);
    } else if (id < N_COPY + N_WRF) {
        // g_wrfh: block = (nb*4+chunk)*9+s, u4 = ((p*2+kt)*32+lane), word j:
        //   nt = p*2+(j>>1), reg = j&1
        //   half2 = (W[n][c], W[n][c+1]), n = nb*128+nt*8+lane/4,
        //   c = chunk*32 + kt*16 + (lane&3)*2 + reg*8
        int idx3 = id - N_COPY;
        int blk = idx3 >> 11, within = idx3 & 2047;
        int s = blk % 9, t = blk / 9;
        int chunk = t & 3, nb = t >> 2;
        int u4 = within >> 2, j = within & 3;
        int lane = u4 & 31, t2 = u4 >> 5;
        int kt = t2 & 1, p = t2 >> 1;
        int nt = p * 2 + (j >> 1), reg = j & 1;
        int n = nb * 128 + nt * 8 + (lane >> 2);
        int c = chunk * 32 + kt * 16 + (lane & 3) * 2 + reg * 8;
        __half2 hv = __floats2half2_rn(W[(n * CIN + c) * 9 + s],
                                       W[(n * CIN + c + 1) * 9 + s]);
        g_wrfh[idx3] = *(uint32_t*)&hv;
    }
}

// ---------------- helpers ----------------
__device__ __forceinline__ void mma_f16(float* d, const uint32_t* a, const uint32_t* b) {
    asm volatile(
        "mma.sync.aligned.m16n8k16.row.col.f32.f16.f16.f32 "
        "{%0,%1,%2,%3}, {%4,%5,%6,%7}, {%8,%9}, {%0,%1,%2,%3};"
        : "+f"(d[0]), "+f"(d[1]), "+f"(d[2]), "+f"(d[3])
        : "r"(a[0]), "r"(a[1]), "r"(a[2]), "r"(a[3]), "r"(b[0]), "r"(b[1]));
}
__device__ __forceinline__ void cp_async16(uint32_t sdst, const void* gsrc) {
    asm volatile("cp.async.cg.shared.global [%0], [%1], 16;" :: "r"(sdst), "l"(gsrc));
}
__device__ __forceinline__ uint32_t smem_u32(const void* p) {
    uint32_t a;
    asm("{ .reg .u64 t; cvta.to.shared.u64 t, %1; cvt.u32.u64 %0, t; }" : "=r"(a) : "l"(p));
    return a;
}
__device__ __forceinline__ int chunk_of(int r) {
    return (r >= 27) ? 3 : (r >= 18) ? 2 : (r >= 9) ? 1 : 0;
}

// one shift-round of MMA work
__device__ __forceinline__ void compute_round(
    const char* smem, int chunk, int off, int bofs,
    int wm, int wn, int lane, float acc[2][8][4])
{
    const uint32_t* sA = (const uint32_t*)(smem + (chunk & 1) * SA_BYTES);
    const uint4* sB4 = (const uint4*)(smem + ABUFS + bofs);
    const int qb = off + wm * 32 + (lane >> 2);
    #pragma unroll
    for (int kt = 0; kt < 2; kt++) {
        const uint32_t* arow = sA + (kt * 8 + (lane & 3)) * AQ;
        uint32_t afr[2][4];
        #pragma unroll
        for (int mt = 0; mt < 2; mt++) {
            const int q = qb + mt * 16;
            afr[mt][0] = arow[q];
            afr[mt][1] = arow[q + 8];
            afr[mt][2] = arow[4 * AQ + q];
            afr[mt][3] = arow[4 * AQ + q + 8];
        }
        uint4 bfr[4];
        #pragma unroll
        for (int c4 = 0; c4 < 4; c4++)
            bfr[c4] = sB4[((wn * 4 + c4) * 2 + kt) * 32 + lane];
        #pragma unroll
        for (int mt = 0; mt < 2; mt++)
            #pragma unroll
            for (int c4 = 0; c4 < 4; c4++) {
                mma_f16(acc[mt][c4 * 2],     afr[mt], (const uint32_t*)&bfr[c4]);
                mma_f16(acc[mt][c4 * 2 + 1], afr[mt], ((const uint32_t*)&bfr[c4]) + 2);
            }
    }
}

// ---------------- main ----------------
__global__ void __launch_bounds__(256, 2)
conv_main(const float* __restrict__ bias, float* __restrict__ out) {
    extern __shared__ char smem[];
    const uint32_t smem_b = smem_u32(smem);
    const int tid  = threadIdx.x;
    const int lane = tid & 31;
    const int wid  = tid >> 5;
    const int wm   = wid & 3;          // 4 m-warps: 32 px each
    const int wn   = wid >> 2;         // 2 n-warps: 64 couts each
    const int bb   = blockIdx.z;
    const int nb   = blockIdx.y;       // 0/1
    const int q0   = blockIdx.x * 128;

    const __half2* xpbh = g_xpadh + (long)bb * 64 * CSTRIDE;

    float acc[2][8][4];
    #pragma unroll
    for (int i = 0; i < 2; i++)
        #pragma unroll
        for (int j = 0; j < 8; j++)
            #pragma unroll
            for (int k = 0; k < 4; k++) acc[i][j][k] = 0.0f;

    // A stage: 16 c2-rows x 62 x 16B into buffer sel
    #define STAGE_A(chunk, sel)                                                    \
        do {                                                                       \
            const __half2* asrc = xpbh + (long)((chunk) * 16) * CSTRIDE + q0;      \
            _Pragma("unroll")                                                      \
            for (int it = 0; it < 4; it++) {                                       \
                int aid = it * 256 + tid;                                          \
                if (aid < 16 * 62) {                                               \
                    int row = aid / 62, col = aid - row * 62;                      \
                    cp_async16(smem_b + (sel) * SA_BYTES + (row * AQ + col * 4) * 4, \
                               asrc + (long)row * CSTRIDE + col * 4);              \
                }                                                                  \
            }                                                                      \
        } while (0)

    // stage B for one shift-round r into quad buffer ((r>>2)&1), slot (r&3)
    #define STAGE_B1(r)                                                            \
        do {                                                                       \
            const int ch = chunk_of(r), sh = (r) - 9 * ch;                         \
            const uint32_t* src = g_wrfh                                           \
                + ((size_t)((nb * 4 + ch) * 9 + sh)) * 2048 + tid * 4;             \
            uint32_t dst = smem_b + ABUFS + (((r) >> 2) & 1) * SBQ_BYTES           \
                           + ((r) & 3) * 8192 + tid * 16;                          \
            cp_async16(dst, src);                                                  \
            cp_async16(dst + 4096, src + 1024);                                    \
        } while (0)

    // prologue: window 0 data (B rounds 0..3, A chunk 0 -> buf 0)
    STAGE_B1(0); STAGE_B1(1); STAGE_B1(2); STAGE_B1(3);
    STAGE_A(0, 0);
    asm volatile("cp.async.commit_group;" ::: "memory");

    for (int w = 0; w < NWIN; w++) {
        // wait for this window's data (committed one window ago)
        asm volatile("cp.async.wait_group 0;" ::: "memory");
        __syncthreads();

        // round 4w first — staging issue cost then hides under its MMAs
        {
            const int r  = 4 * w;
            const int ch = chunk_of(r);
            const int s  = r - 9 * ch;
            compute_round(smem, ch, (s / 3) * PW + (s % 3),
                          (w & 1) * SBQ_BYTES, wm, wn, lane, acc);
        }

        // stage next window (post-barrier => ring-2 safe: every warp past
        // this barrier finished window w-1, the only reader of (w+1)%2).
        // A: buf1 last read r17 (win 4) -> staged win 5; buf0 last read r8
        // (win 2) -> staged win 3; chunk1->buf1 staged win 0 (round 0 of
        // win 0 reads buf0 only). STS/cp.async visible after next barrier.
        if (w + 1 < NWIN) {
            const int r0 = 4 * (w + 1);
            STAGE_B1(r0); STAGE_B1(r0 + 1); STAGE_B1(r0 + 2); STAGE_B1(r0 + 3);
            if (w == 0)      STAGE_A(1, 1);
            else if (w == 3) STAGE_A(2, 0);
            else if (w == 5) STAGE_A(3, 1);
            asm volatile("cp.async.commit_group;" ::: "memory");
        }

        // rounds 4w+1 .. 4w+3
        const int qbase = (w & 1) * SBQ_BYTES;
        #pragma unroll
        for (int j = 1; j < 4; j++) {
            const int r  = 4 * w + j;
            const int ch = chunk_of(r);
            const int s  = r - 9 * ch;
            compute_round(smem, ch, (s / 3) * PW + (s % 3), qbase + j * 8192,
                          wm, wn, lane, acc);
        }
    }

    // ---- epilogue ----
    const long obb = (long)bb * COUT * (HW * HW);
    #pragma unroll
    for (int nt = 0; nt < 8; nt++) {
        const int n = nb * 128 + wn * 64 + nt * 8 + (lane & 3) * 2;
        const float bv0 = __ldg(bias + n);
        const float bv1 = __ldg(bias + n + 1);
        const long onb = obb + (long)n * (HW * HW);
        #pragma unroll
        for (int mt = 0; mt < 2; mt++) {
            const int m = q0 + wm * 32 + mt * 16 + (lane >> 2);
            {
                const int h = m / PW, w = m % PW;
                if (h < HW && w < HW) {
                    const long o = onb + h * HW + w;
                    out[o]           = acc[mt][nt][0] + bv0;
                    out[o + HW * HW] = acc[mt][nt][1] + bv1;
                }
            }
            {
                const int m2 = m + 8;
                const int h = m2 / PW, w = m2 % PW;
                if (h < HW && w < HW) {
                    const long o = onb + h * HW + w;
                    out[o]           = acc[mt][nt][2] + bv0;
                    out[o + HW * HW] = acc[mt][nt][3] + bv1;
                }
            }
        }
    }
}

// ---------------- launch ----------------
extern "C" void kernel_launch(void* const* d_in, const int* in_sizes, int n_in,
                              void* d_out, int out_size) {
    const float* x  = (const float*)d_in[0];
    const float* W  = (const float*)d_in[1];
    const float* bi = (const float*)d_in[2];
    float* out      = (float*)d_out;

    cudaFuncSetAttribute(conv_main, cudaFuncAttributeMaxDynamicSharedMemorySize,
                         SMEM_TOTAL);

    const int prep_total = N_COPY + N_WRF;
    prep_kernel<<<(prep_total + 255) / 256, 256>>>(x, W);
    conv_main<<<dim3(MTILES, 2, BATCH), 256, SMEM_TOTAL>>>(bi, out);
}